// round 15
// baseline (speedup 1.0000x reference)
#include <cuda_runtime.h>
#include <cuda_fp16.h>
#include <cstdint>

// Problem constants (GATAuto: B=8, N=2048, Fin=128, H=[128,128,64], C=128)
#define BB 8
#define NN 2048
#define RTOT (BB*NN)          // 16384 rows
#define ZSPLIT 4
#define JT_PER ((NN/64)/ZSPLIT)   // 8 j-tiles per z-chunk
#define IGROUPS 4                 // i-groups of 512 rows

// ---------------- scratch (device globals; no allocation allowed) ----------
__device__ __align__(16) __half g_hh[128 * RTOT];          // h transposed fp16 [o][row]
__device__ __align__(16) float  g_pd[(size_t)ZSPLIT * RTOT * 128];  // partial D
__device__ float    g_ps[ZSPLIT * RTOT];                   // partial row sums
__device__ float    g_es[RTOT], g_r[RTOT];                 // es, exp(-0.8 es)
__device__ float    g_ed[RTOT], g_v[RTOT], g_q[RTOT];      // ed, exp(ed), exp(0.2 ed)
__device__ unsigned g_mask[NN * (NN / 32)];                // adjacency bitmask, 512KB
__device__ float    g_part[256 * 1024];                    // final-linear split-K partials

// ======================= warp MMA helpers (baseline PTX) =====================
__device__ __forceinline__ uint32_t smem_to_u32(const void* p) {
    uint32_t a;
    asm("{ .reg .u64 t; cvta.to.shared.u64 t, %1; cvt.u32.u64 %0, t; }" : "=r"(a) : "l"(p));
    return a;
}
__device__ __forceinline__ void ldmx4(uint32_t& r0, uint32_t& r1, uint32_t& r2, uint32_t& r3,
                                      uint32_t addr) {
    asm volatile("ldmatrix.sync.aligned.m8n8.x4.shared.b16 {%0,%1,%2,%3}, [%4];"
                 : "=r"(r0), "=r"(r1), "=r"(r2), "=r"(r3) : "r"(addr));
}
__device__ __forceinline__ void mma_f16(float* d, uint32_t a0, uint32_t a1, uint32_t a2,
                                        uint32_t a3, uint32_t b0, uint32_t b1) {
    asm volatile("mma.sync.aligned.m16n8k16.row.col.f32.f16.f16.f32 "
                 "{%0,%1,%2,%3}, {%4,%5,%6,%7}, {%8,%9}, {%0,%1,%2,%3};"
                 : "+f"(d[0]), "+f"(d[1]), "+f"(d[2]), "+f"(d[3])
                 : "r"(a0), "r"(a1), "r"(a2), "r"(a3), "r"(b0), "r"(b1));
}
#define CP_ASYNC16(dst, src) \
    asm volatile("cp.async.ca.shared.global [%0], [%1], 16;" :: "r"(dst), "l"(src))
#define CP_COMMIT() asm volatile("cp.async.commit_group;" ::: "memory")
#define CP_WAIT0()  asm volatile("cp.async.wait_group 0;" ::: "memory")

// fp16x2 packed ops on u32 registers
__device__ __forceinline__ uint32_t hadd2u(uint32_t a, uint32_t b) {
    uint32_t d; asm("add.f16x2 %0, %1, %2;" : "=r"(d) : "r"(a), "r"(b)); return d;
}
__device__ __forceinline__ uint32_t hmul2u(uint32_t a, uint32_t b) {
    uint32_t d; asm("mul.f16x2 %0, %1, %2;" : "=r"(d) : "r"(a), "r"(b)); return d;
}
__device__ __forceinline__ uint32_t hmin2u(uint32_t a, uint32_t b) {
    uint32_t d; asm("min.f16x2 %0, %1, %2;" : "=r"(d) : "r"(a), "r"(b)); return d;
}
__device__ __forceinline__ uint32_t hge2_mask(uint32_t a, uint32_t b) {
    uint32_t d; asm("set.ge.u32.f16x2 %0, %1, %2;" : "=r"(d) : "r"(a), "r"(b)); return d;
}

// ---------------- adjacency bitmask ----------------------------------------
__global__ void build_mask_kernel(const float* __restrict__ adj) {
    int w    = blockIdx.x * 8 + (threadIdx.x >> 5);
    int lane = threadIdx.x & 31;
    int row  = w >> 6;
    int wc   = w & 63;
    float av = adj[(size_t)row * NN + wc * 32 + lane];
    unsigned m = __ballot_sync(0xffffffffu, av > 0.0f);
    if (lane == 0) g_mask[w] = m;
}

// ---------------- h = X @ W, transposed fp16 out + fused stats --------------
// BM=32, 128 threads, thread tile 4 x TN (W reuse x4). Grid 512 for occupancy.
// X tile staged ONCE up-front (fused 4-partial sum + relu, coalesced float4).
template <int FOUT, int FUSE>
__global__ __launch_bounds__(128) void sgemm_h_kernel(
    const float* __restrict__ X, const float* __restrict__ W,
    const float* __restrict__ as, const float* __restrict__ ad,
    __half* __restrict__ Hh)
{
    constexpr int TN = FOUT / 16;
    constexpr int XP = 132;                      // padded X row (floats)
    constexpr uint32_t OFF_X  = 0;               // 32 x 132 f32 = 16896 B
    constexpr uint32_t OFF_W  = 32 * XP * 4;     // 2 x 16 x (FOUT+4) f32
    constexpr uint32_t OFF_I  = OFF_W + 2 * 16 * (FOUT + 4) * 4;  // 32 f32

    extern __shared__ char smem[];
    float* sX   = (float*)(smem + OFF_X);        // [row][col] padded XP
    float* sWb  = (float*)(smem + OFF_W);        // [buf][k][FOUT+4]
    float* sInv = (float*)(smem + OFF_I);
    float* sRed1 = (float*)(smem + OFF_X);              // alias (32 x 17)
    float* sRed2 = (float*)(smem + OFF_X + 32 * 17 * 4);

    const int tid  = threadIdx.x;                // [0,128)
    const int row0 = blockIdx.x * 32;
    const int tr   = tid >> 4;   // 0..7, rows tr*4 .. tr*4+3
    const int tc   = tid & 15;

    if (FUSE) {
        if (tid < 32) {
            int gr = row0 + tid;
            float rs = g_ps[gr] + g_ps[RTOT + gr] + g_ps[2 * RTOT + gr] + g_ps[3 * RTOT + gr];
            sInv[tid] = 1.0f / rs;
        }
        __syncthreads();
    }

    // ---- Phase A: stage entire 32x128 X tile (fused sum+relu if FUSE) ----
#pragma unroll
    for (int t = 0; t < 8; t++) {
        int idx = tid + t * 128;       // 1024 float4 slots
        int row = idx >> 5;            // 32 float4 per row
        int c4  = idx & 31;
        size_t off = (size_t)(row0 + row) * 128 + c4 * 4;
        float4 v;
        if (FUSE) {
            float4 a  = *(const float4*)(g_pd + off);
            float4 b2 = *(const float4*)(g_pd + (size_t)RTOT * 128 + off);
            float4 c2 = *(const float4*)(g_pd + 2 * (size_t)RTOT * 128 + off);
            float4 d2 = *(const float4*)(g_pd + 3 * (size_t)RTOT * 128 + off);
            float inv = sInv[row];
            v.x = fmaxf((a.x + b2.x + c2.x + d2.x) * inv, 0.0f);
            v.y = fmaxf((a.y + b2.y + c2.y + d2.y) * inv, 0.0f);
            v.z = fmaxf((a.z + b2.z + c2.z + d2.z) * inv, 0.0f);
            v.w = fmaxf((a.w + b2.w + c2.w + d2.w) * inv, 0.0f);
        } else {
            v = *(const float4*)(X + off);
        }
        *(float4*)&sX[row * XP + c4 * 4] = v;
    }

    // ---- W pipeline (register prefetch + smem double buffer) ----
    float wr[2 * TN];
    auto ldg_W = [&](int f0) {
#pragma unroll
        for (int t = 0; t < 2 * TN; t++) {
            int idx = tid + t * 128;
            wr[t] = W[(size_t)(f0 + idx / FOUT) * FOUT + idx % FOUT];
        }
    };
    auto st_W = [&](int buf) {
#pragma unroll
        for (int t = 0; t < 2 * TN; t++) {
            int idx = tid + t * 128;
            sWb[(size_t)buf * 16 * (FOUT + 4) + (idx / FOUT) * (FOUT + 4) + idx % FOUT] = wr[t];
        }
    };

    float acc[4][TN];
#pragma unroll
    for (int r = 0; r < 4; r++)
#pragma unroll
        for (int c = 0; c < TN; c++) acc[r][c] = 0.0f;

    ldg_W(0);
    st_W(0);
    __syncthreads();   // covers Phase A stores + W buf 0

    for (int c8 = 0; c8 < 8; c8++) {
        if (c8 < 7) ldg_W((c8 + 1) * 16);
        const float* wbuf = sWb + (size_t)(c8 & 1) * 16 * (FOUT + 4);
        const float* x0 = &sX[(tr * 4 + 0) * XP + c8 * 16];
        const float* x1 = &sX[(tr * 4 + 1) * XP + c8 * 16];
        const float* x2 = &sX[(tr * 4 + 2) * XP + c8 * 16];
        const float* x3 = &sX[(tr * 4 + 3) * XP + c8 * 16];
#pragma unroll
        for (int k = 0; k < 16; k++) {
            float ra0 = x0[k], ra1 = x1[k], ra2 = x2[k], ra3 = x3[k];
            float rb[TN];
            if (TN == 8) {
                *(float4*)&rb[0] = *(const float4*)&wbuf[k * (FOUT + 4) + tc * 8];
                *(float4*)&rb[4] = *(const float4*)&wbuf[k * (FOUT + 4) + tc * 8 + 4];
            } else {
                *(float4*)&rb[0] = *(const float4*)&wbuf[k * (FOUT + 4) + tc * 4];
            }
#pragma unroll
            for (int c = 0; c < TN; c++) {
                acc[0][c] += ra0 * rb[c];
                acc[1][c] += ra1 * rb[c];
                acc[2][c] += ra2 * rb[c];
                acc[3][c] += ra3 * rb[c];
            }
        }
        if (c8 < 7) {
            st_W((c8 & 1) ^ 1);
            __syncthreads();
        }
    }

    // ---- stats partials (fp32 acc) ----
    float s1[4] = {0, 0, 0, 0}, s2[4] = {0, 0, 0, 0};
#pragma unroll
    for (int c = 0; c < TN; c++) {
        float av = __ldg(as + tc * TN + c);
        float dv = __ldg(ad + tc * TN + c);
#pragma unroll
        for (int r = 0; r < 4; r++) {
            s1[r] += acc[r][c] * av;
            s2[r] += acc[r][c] * dv;
        }
    }
    __syncthreads();   // X region dead; safe to alias sRed
#pragma unroll
    for (int r = 0; r < 4; r++) {
        sRed1[(tr * 4 + r) * 17 + tc] = s1[r];
        sRed2[(tr * 4 + r) * 17 + tc] = s2[r];
    }

    // transposed fp16 store (4 rows per thread)
#pragma unroll
    for (int c = 0; c < TN; c++) {
        int col = tc * TN + c;
        __half2 h01 = __float22half2_rn(make_float2(acc[0][c], acc[1][c]));
        __half2 h23 = __float22half2_rn(make_float2(acc[2][c], acc[3][c]));
        size_t off = (size_t)col * RTOT + row0 + tr * 4;
        *(__half2*)(Hh + off)     = h01;
        *(__half2*)(Hh + off + 2) = h23;
    }

    __syncthreads();
    if (tid < 32) {
        float t1 = 0.0f, t2 = 0.0f;
#pragma unroll
        for (int t = 0; t < 16; t++) { t1 += sRed1[tid * 17 + t]; t2 += sRed2[tid * 17 + t]; }
        int gr = row0 + tid;
        g_es[gr] = t1; g_r[gr] = __expf(-0.8f * t1);
        g_ed[gr] = t2; g_v[gr] = __expf(t2); g_q[gr] = __expf(0.2f * t2);
    }
}

// ---------------- fused masked-attention, B-resident, 16 warps --------------
// Block = (i-group of 512 rows) x (z-chunk of 512 j), 512 threads.
// Warp-group 0 (warps 0-7): i-tiles 0,1; warp-group 1 (warps 8-15): i-tiles 2,3.
// Groups share resident B tiles (read-only); each owns its P tile.
// Row-normalized P: P'_ij = mask ? ((es_i+ed_j>=0) ? v_j : r_i*q_j) : 0
template <int FOUT>
__global__ __launch_bounds__(512, 1) void attn_mma_kernel(
    const __half* __restrict__ Bh)
{
    constexpr int ROWB = 144;                    // P row stride (bytes)
    constexpr uint32_t PSZ = 128 * ROWB;         // one P tile (18432 B)
    constexpr uint32_t OFF_ES  = 0;              // 512 f32
    constexpr uint32_t OFF_R   = 2048;           // 512 f32
    constexpr uint32_t OFF_EDH = 4096;           // 512 half
    constexpr uint32_t OFF_VH  = 5120;           // 512 half
    constexpr uint32_t OFF_QH  = 6144;           // 512 half
    constexpr uint32_t OFF_P   = 7168;           // 2 x P tile
    constexpr uint32_t OFF_B   = OFF_P + 2 * PSZ;        // 44032
    constexpr uint32_t BUFSTRIDE = (uint32_t)FOUT * 128; // per fp16 tile
    constexpr uint32_t ONES  = 0x3C003C00u;      // fp16x2 {1,1}
    constexpr uint32_t CLAMP = 0x7B537B53u;      // fp16x2 {60000,60000}

    extern __shared__ char smem[];
    const uint32_t sb = smem_to_u32(smem);
    const int tid  = threadIdx.x;              // [0,512)
    const int wid  = tid >> 5;                 // [0,16)
    const int lane = tid & 31;
    const int grp  = wid >> 3;                 // warp-group 0/1
    const int wg   = wid & 7;                  // warp within group
    const int tig  = tid & 255;                // thread within group

    const int ig   = blockIdx.x;            // i-group (512 rows)
    const int b    = blockIdx.y;
    const int z    = blockIdx.z;
    const int base = b * NN;
    const int irow0 = ig * 512;              // node index of group start
    const int jbase = base + z * (JT_PER * 64);

    float*  ses  = (float*)(smem + OFF_ES);
    float*  sr   = (float*)(smem + OFF_R);
    __half* sedh = (__half*)(smem + OFF_EDH);
    __half* svh  = (__half*)(smem + OFF_VH);
    __half* sqh  = (__half*)(smem + OFF_QH);

    // ---- prologue staging (512 i-rows + 512 j-stats) ----
    {
        int i = base + irow0 + tid;
        ses[tid] = g_es[i];
        sr[tid]  = g_r[i];
        sedh[tid] = __float2half(g_ed[jbase + tid]);
        svh[tid]  = __float2half(fminf(g_v[jbase + tid], 60000.0f));
        sqh[tid]  = __float2half(g_q[jbase + tid]);
    }

    // ---- load ALL 8 B tiles once (cp.async, swizzled 128B rows) ----
    {
        constexpr int TOTCH = JT_PER * FOUT * 8;   // 16B chunks
#pragma unroll
        for (int t = 0; t < TOTCH / 512; t++) {
            int idx  = tid + t * 512;
            int tile = idx / (FOUT * 8);
            int rem  = idx % (FOUT * 8);
            int o = rem >> 3, c = rem & 7;
            uint32_t dst = sb + OFF_B + tile * BUFSTRIDE + o * 128
                         + (uint32_t)((c ^ (o & 7)) << 4);
            const char* src = (const char*)(Bh + (size_t)o * RTOT + jbase + tile * 64) + c * 16;
            CP_ASYNC16(dst, src);
        }
    }
    CP_COMMIT();

    // per-thread P-build coordinates (within group)
    const int iP = tig >> 1;                 // local row [0,128)
    const int jh = tig & 1;
    char* dstP = smem + OFF_P + grp * PSZ + iP * ROWB + jh * 64;

    // ldmatrix fixed addresses
    const int arow  = wg * 16 + (lane & 7) + (((lane >> 3) & 1) << 3);
    const int akoff = (lane >> 4) << 4;
    const uint32_t aBase = sb + OFF_P + grp * PSZ + arow * ROWB + akoff;
    const int brow = (lane & 7) + ((lane >> 4) << 3);
    const int bsel = (lane >> 3) & 1;

    constexpr int NT = FOUT / 8;

    CP_WAIT0();
    __syncthreads();   // B tiles + staging visible; ONLY block barrier

    for (int mm = 0; mm < 2; mm++) {
        const int m = grp * 2 + mm;          // i-tile index for this group
        const int iloc = m * 128;            // local row offset within group

        // per-thread row constants for this i-tile
        uint32_t es2, ri2;
        {
            __half eh = __float2half(ses[iloc + iP]);
            __half rh = __float2half(fminf(sr[iloc + iP], 60000.0f));
            uint16_t eu = __half_as_ushort(eh), ru = __half_as_ushort(rh);
            es2 = (uint32_t)eu | ((uint32_t)eu << 16);
            ri2 = (uint32_t)ru | ((uint32_t)ru << 16);
        }
        // mask words for this row, all 8 local j-tiles
        unsigned mw[JT_PER];
        {
            const unsigned* mrow = g_mask + (size_t)(irow0 + iloc + iP) * (NN / 32)
                                 + z * (JT_PER * 2) + jh;
#pragma unroll
            for (int l = 0; l < JT_PER; l++) mw[l] = mrow[l * 2];
        }

        float acc[NT][4];
#pragma unroll
        for (int n = 0; n < NT; n++)
#pragma unroll
            for (int q = 0; q < 4; q++) acc[n][q] = 0.0f;
        float accRS[4] = {0.f, 0.f, 0.f, 0.f};

        for (int l = 0; l < JT_PER; l++) {
            // build P rows (warp-local ownership), fp16x2 vectorized
            {
                const unsigned mm0 = mw[l];
                const __half* edl = sedh + l * 64 + (jh << 5);
                const __half* vl  = svh  + l * 64 + (jh << 5);
                const __half* ql  = sqh  + l * 64 + (jh << 5);
#pragma unroll
                for (int jj = 0; jj < 32; jj += 4) {
                    uint2 ed = *(const uint2*)(edl + jj);
                    uint2 vv = *(const uint2*)(vl + jj);
                    uint2 qq = *(const uint2*)(ql + jj);
                    uint32_t t0 = hadd2u(es2, ed.x);
                    uint32_t t1 = hadd2u(es2, ed.y);
                    uint32_t ge0 = hge2_mask(t0, 0u);
                    uint32_t ge1 = hge2_mask(t1, 0u);
                    uint32_t lo0 = hmul2u(ri2, qq.x);
                    uint32_t lo1 = hmul2u(ri2, qq.y);
                    uint32_t a0 = (vv.x & ge0) | (lo0 & ~ge0);
                    uint32_t a1 = (vv.y & ge1) | (lo1 & ~ge1);
                    uint32_t mb = mm0 >> jj;
                    a0 &= ((mb & 1u) * 0xFFFFu) | (((mb >> 1) & 1u) * 0xFFFF0000u);
                    a1 &= (((mb >> 2) & 1u) * 0xFFFFu) | (((mb >> 3) & 1u) * 0xFFFF0000u);
                    a0 = hmin2u(a0, CLAMP);
                    a1 = hmin2u(a1, CLAMP);
                    *(uint2*)(dstP + jj * 2) = make_uint2(a0, a1);
                }
            }
            __syncwarp();

            // MMA from resident B tile l
            const uint32_t bB = sb + OFF_B + l * BUFSTRIDE;
#pragma unroll
            for (int kk = 0; kk < 4; kk++) {
                uint32_t ah0, ah1, ah2, ah3;
                ldmx4(ah0, ah1, ah2, ah3, aBase + kk * 32);
                mma_f16(accRS, ah0, ah1, ah2, ah3, ONES, ONES);
                int cIdx = kk * 2 + bsel;
#pragma unroll
                for (int np = 0; np < NT / 2; np++) {
                    int r = np * 16 + brow;
                    uint32_t ba = bB + r * 128 + (uint32_t)((cIdx ^ (r & 7)) << 4);
                    uint32_t bh0, bh1, bh2, bh3;
                    ldmx4(bh0, bh1, bh2, bh3, ba);
                    mma_f16(acc[np * 2],     ah0, ah1, ah2, ah3, bh0, bh1);
                    mma_f16(acc[np * 2 + 1], ah0, ah1, ah2, ah3, bh2, bh3);
                }
            }
            __syncwarp();   // P reads done before next overwrite (warp-local)
        }

        // partial row sums (quad leader writes)
        if ((lane & 3) == 0) {
            int r0 = wg * 16 + (lane >> 2);
            g_ps[z * RTOT + base + irow0 + iloc + r0]     = accRS[0];
            g_ps[z * RTOT + base + irow0 + iloc + r0 + 8] = accRS[2];
        }

        // partial D store
        {
            int r0 = wg * 16 + (lane >> 2);
            int r1 = r0 + 8;
            size_t rb = (size_t)z * RTOT * 128 + (size_t)(base + irow0 + iloc) * FOUT;
            float* p0 = g_pd + rb + (size_t)r0 * FOUT + (lane & 3) * 2;
            float* p1 = g_pd + rb + (size_t)r1 * FOUT + (lane & 3) * 2;
#pragma unroll
            for (int n = 0; n < NT; n++) {
                *(float2*)(p0 + n * 8) = make_float2(acc[n][0], acc[n][1]);
                *(float2*)(p1 + n * 8) = make_float2(acc[n][2], acc[n][3]);
            }
        }
    }
}

// ---------------- final linear (fused layer-3 combine) ----------------------
// X[b][k] = relu((sum_z pd)/sum_z ps), staged once per block into smem.
__global__ __launch_bounds__(128) void final_partial_kernel(
    const float* __restrict__ Wlin)
{
    __shared__ float Xs[4096];       // 8 batches x 512 k
    __shared__ float sInvF[64];      // 8 batches x 8 rows
    const int c  = threadIdx.x;
    const int s  = blockIdx.x;
    const int k0 = s * 512;

    if (c < 64) {
        int bb = c >> 3, rr = c & 7;
        int rown = bb * NN + (k0 >> 6) + rr;
        float rs = g_ps[rown] + g_ps[RTOT + rown] + g_ps[2 * RTOT + rown] + g_ps[3 * RTOT + rown];
        sInvF[c] = 1.0f / rs;
    }
    __syncthreads();

#pragma unroll
    for (int t = 0; t < 8; t++) {
        int idx = (c + t * 128) * 4;       // float4 granularity, 0..4095
        int bb  = idx >> 9;
        int kk  = idx & 511;
        size_t off = (size_t)bb * 131072 + k0 + kk;
        float4 a  = *(const float4*)(g_pd + off);
        float4 b2 = *(const float4*)(g_pd + (size_t)RTOT * 128 + off);
        float4 c2 = *(const float4*)(g_pd + 2 * (size_t)RTOT * 128 + off);
        float4 d2 = *(const float4*)(g_pd + 3 * (size_t)RTOT * 128 + off);
        float inv = sInvF[(bb << 3) + (kk >> 6)];
        float4 v;
        v.x = fmaxf((a.x + b2.x + c2.x + d2.x) * inv, 0.0f);
        v.y = fmaxf((a.y + b2.y + c2.y + d2.y) * inv, 0.0f);
        v.z = fmaxf((a.z + b2.z + c2.z + d2.z) * inv, 0.0f);
        v.w = fmaxf((a.w + b2.w + c2.w + d2.w) * inv, 0.0f);
        *(float4*)&Xs[idx] = v;
    }
    __syncthreads();

    float acc[8] = {0, 0, 0, 0, 0, 0, 0, 0};
    for (int kk = 0; kk < 512; kk++) {
        float w = Wlin[(size_t)(k0 + kk) * 128 + c];
#pragma unroll
        for (int bb = 0; bb < 8; bb++) acc[bb] += Xs[bb * 512 + kk] * w;
    }
#pragma unroll
    for (int bb = 0; bb < 8; bb++) g_part[s * 1024 + bb * 128 + c] = acc[bb];
}

__global__ __launch_bounds__(256) void final_reduce_kernel(
    const float* __restrict__ blin, float* __restrict__ out)
{
    int idx = blockIdx.x * 256 + threadIdx.x;
    if (idx < 1024) {
        float s = 0.0f;
        for (int sp = 0; sp < 256; sp++) s += g_part[sp * 1024 + idx];
        out[idx] = s + blin[idx & 127];
    }
}

// ---------------- host driver ------------------------------------------------
extern "C" void kernel_launch(void* const* d_in, const int* in_sizes, int n_in,
                              void* d_out, int out_size)
{
    const float* x    = (const float*)d_in[0];
    const float* adj  = (const float*)d_in[1];
    const float* W1   = (const float*)d_in[2];
    const float* a1s  = (const float*)d_in[3];
    const float* a1d  = (const float*)d_in[4];
    const float* W2   = (const float*)d_in[5];
    const float* a2s  = (const float*)d_in[6];
    const float* a2d  = (const float*)d_in[7];
    const float* W3   = (const float*)d_in[8];
    const float* a3s  = (const float*)d_in[9];
    const float* a3d  = (const float*)d_in[10];
    const float* Wlin = (const float*)d_in[11];
    const float* blin = (const float*)d_in[12];

    void* phh; cudaGetSymbolAddress(&phh, g_hh);
    __half* hh = (__half*)phh;

    constexpr int SM128 = 44032 + 8 * 128 * 128;  // attn 175104
    constexpr int SM64  = 44032 + 8 * 64 * 128;   // attn 109568
    cudaFuncSetAttribute(attn_mma_kernel<128>, cudaFuncAttributeMaxDynamicSharedMemorySize, SM128);
    cudaFuncSetAttribute(attn_mma_kernel<64>,  cudaFuncAttributeMaxDynamicSharedMemorySize, SM64);

    // sgemm dynamic smem: X(32*132*4) + W(2*16*(FOUT+4)*4) + sInv(128)
    constexpr int SG128 = 32 * 132 * 4 + 2 * 16 * 132 * 4 + 128;  // 33920
    constexpr int SG64  = 32 * 132 * 4 + 2 * 16 * 68 * 4 + 128;   // 25728
    cudaFuncSetAttribute(sgemm_h_kernel<128, 0>, cudaFuncAttributeMaxDynamicSharedMemorySize, SG128);
    cudaFuncSetAttribute(sgemm_h_kernel<128, 1>, cudaFuncAttributeMaxDynamicSharedMemorySize, SG128);
    cudaFuncSetAttribute(sgemm_h_kernel<64, 1>,  cudaFuncAttributeMaxDynamicSharedMemorySize, SG64);

    build_mask_kernel<<<16384, 256>>>(adj);

    // layer 1 (128 -> 128): reads x directly
    sgemm_h_kernel<128, 0><<<512, 128, SG128>>>(x, W1, a1s, a1d, hh);
    attn_mma_kernel<128><<<dim3(IGROUPS, 8, ZSPLIT), 512, SM128>>>(hh);

    // layer 2 (128 -> 128): reads fused layer-1 partials
    sgemm_h_kernel<128, 1><<<512, 128, SG128>>>(nullptr, W2, a2s, a2d, hh);
    attn_mma_kernel<128><<<dim3(IGROUPS, 8, ZSPLIT), 512, SM128>>>(hh);

    // layer 3 (128 -> 64): reads fused layer-2 partials
    sgemm_h_kernel<64, 1><<<512, 128, SG64>>>(nullptr, W3, a3s, a3d, hh);
    attn_mma_kernel<64><<<dim3(IGROUPS, 8, ZSPLIT), 512, SM64>>>(hh);

    // final linear (fused layer-3 combine)
    final_partial_kernel<<<256, 128>>>(Wlin);
    final_reduce_kernel<<<4, 256>>>(blin, (float*)d_out);
}

// round 16
// speedup vs baseline: 1.0404x; 1.0404x over previous
#include <cuda_runtime.h>
#include <cuda_fp16.h>
#include <cstdint>

// Problem constants (GATAuto: B=8, N=2048, Fin=128, H=[128,128,64], C=128)
#define BB 8
#define NN 2048
#define RTOT (BB*NN)          // 16384 rows
#define ZSPLIT 4
#define JT_PER ((NN/64)/ZSPLIT)   // 8 j-tiles per z-chunk
#define IGROUPS 4                 // i-groups of 512 rows

// ---------------- scratch (device globals; no allocation allowed) ----------
__device__ __align__(16) __half g_hh[128 * RTOT];          // h transposed fp16 [o][row]
__device__ __align__(16) __half g_pdh[(size_t)ZSPLIT * RTOT * 128];  // normalized partial D (fp16)
__device__ float    g_ps[ZSPLIT * RTOT];                   // partial row sums
__device__ float    g_es[RTOT], g_r[RTOT];                 // es, exp(-0.8 es)
__device__ float    g_ed[RTOT], g_v[RTOT], g_q[RTOT];      // ed, exp(ed), exp(0.2 ed)
__device__ unsigned g_mask[NN * (NN / 32)];                // adjacency bitmask, 512KB
__device__ float    g_part[256 * 1024];                    // final-linear split-K partials

// ======================= warp MMA helpers (baseline PTX) =====================
__device__ __forceinline__ uint32_t smem_to_u32(const void* p) {
    uint32_t a;
    asm("{ .reg .u64 t; cvta.to.shared.u64 t, %1; cvt.u32.u64 %0, t; }" : "=r"(a) : "l"(p));
    return a;
}
__device__ __forceinline__ void ldmx4(uint32_t& r0, uint32_t& r1, uint32_t& r2, uint32_t& r3,
                                      uint32_t addr) {
    asm volatile("ldmatrix.sync.aligned.m8n8.x4.shared.b16 {%0,%1,%2,%3}, [%4];"
                 : "=r"(r0), "=r"(r1), "=r"(r2), "=r"(r3) : "r"(addr));
}
__device__ __forceinline__ void mma_f16(float* d, uint32_t a0, uint32_t a1, uint32_t a2,
                                        uint32_t a3, uint32_t b0, uint32_t b1) {
    asm volatile("mma.sync.aligned.m16n8k16.row.col.f32.f16.f16.f32 "
                 "{%0,%1,%2,%3}, {%4,%5,%6,%7}, {%8,%9}, {%0,%1,%2,%3};"
                 : "+f"(d[0]), "+f"(d[1]), "+f"(d[2]), "+f"(d[3])
                 : "r"(a0), "r"(a1), "r"(a2), "r"(a3), "r"(b0), "r"(b1));
}
#define CP_ASYNC16(dst, src) \
    asm volatile("cp.async.ca.shared.global [%0], [%1], 16;" :: "r"(dst), "l"(src))
#define CP_COMMIT() asm volatile("cp.async.commit_group;" ::: "memory")
#define CP_WAIT0()  asm volatile("cp.async.wait_group 0;" ::: "memory")

// fp16x2 packed ops on u32 registers
__device__ __forceinline__ uint32_t hadd2u(uint32_t a, uint32_t b) {
    uint32_t d; asm("add.f16x2 %0, %1, %2;" : "=r"(d) : "r"(a), "r"(b)); return d;
}
__device__ __forceinline__ uint32_t hmul2u(uint32_t a, uint32_t b) {
    uint32_t d; asm("mul.f16x2 %0, %1, %2;" : "=r"(d) : "r"(a), "r"(b)); return d;
}
__device__ __forceinline__ uint32_t hmin2u(uint32_t a, uint32_t b) {
    uint32_t d; asm("min.f16x2 %0, %1, %2;" : "=r"(d) : "r"(a), "r"(b)); return d;
}
__device__ __forceinline__ uint32_t hge2_mask(uint32_t a, uint32_t b) {
    uint32_t d; asm("set.ge.u32.f16x2 %0, %1, %2;" : "=r"(d) : "r"(a), "r"(b)); return d;
}

// ---------------- adjacency bitmask ----------------------------------------
__global__ void build_mask_kernel(const float* __restrict__ adj) {
    int w    = blockIdx.x * 8 + (threadIdx.x >> 5);
    int lane = threadIdx.x & 31;
    int row  = w >> 6;
    int wc   = w & 63;
    float av = adj[(size_t)row * NN + wc * 32 + lane];
    unsigned m = __ballot_sync(0xffffffffu, av > 0.0f);
    if (lane == 0) g_mask[w] = m;
}

// ---------------- h = X @ W, transposed fp16 out + fused stats --------------
// BM=64, thread tile 4 x TN. FUSE=1: X = relu(sum_z w_z * d_z) from fp16
// normalized partials (w_z = s_z / sum s). X staged ONCE up-front.
template <int FOUT, int FUSE>
__global__ __launch_bounds__(256) void sgemm_h_kernel(
    const float* __restrict__ X, const float* __restrict__ W,
    const float* __restrict__ as, const float* __restrict__ ad,
    __half* __restrict__ Hh)
{
    constexpr int TN = FOUT / 16;
    constexpr int XP = 132;                      // padded X row (floats)
    constexpr uint32_t OFF_X  = 0;               // 64 x 132 f32 = 33792 B
    constexpr uint32_t OFF_W  = 64 * XP * 4;     // 2 x 16 x (FOUT+4) f32
    constexpr uint32_t OFF_I  = OFF_W + 2 * 16 * (FOUT + 4) * 4;  // 64 float4

    extern __shared__ char smem[];
    float*  sX   = (float*)(smem + OFF_X);       // [row][col] padded XP
    float*  sWb  = (float*)(smem + OFF_W);       // [buf][k][FOUT+4]
    float4* sWz  = (float4*)(smem + OFF_I);      // per-row z-weights
    float* sRed1 = (float*)(smem + OFF_X);              // alias (64 x 17)
    float* sRed2 = (float*)(smem + OFF_X + 64 * 17 * 4);

    const int tid  = threadIdx.x;
    const int row0 = blockIdx.x * 64;
    const int tr   = tid >> 4;   // 0..15, rows tr*4 .. tr*4+3
    const int tc   = tid & 15;

    if (FUSE) {
        if (tid < 64) {
            int gr = row0 + tid;
            float s0 = g_ps[gr], s1 = g_ps[RTOT + gr];
            float s2 = g_ps[2 * RTOT + gr], s3 = g_ps[3 * RTOT + gr];
            float inv = 1.0f / (s0 + s1 + s2 + s3);
            sWz[tid] = make_float4(s0 * inv, s1 * inv, s2 * inv, s3 * inv);
        }
        __syncthreads();
    }

    // ---- Phase A: stage entire 64x128 X tile ----
#pragma unroll
    for (int t = 0; t < 8; t++) {
        int idx = tid + t * 256;       // 2048 4-elem slots
        int row = idx >> 5;
        int c4  = idx & 31;
        size_t off = (size_t)(row0 + row) * 128 + c4 * 4;
        float4 v;
        if (FUSE) {
            float4 w = sWz[row];
            uint2 u0 = *(const uint2*)(g_pdh + off);
            uint2 u1 = *(const uint2*)(g_pdh + (size_t)RTOT * 128 + off);
            uint2 u2 = *(const uint2*)(g_pdh + 2 * (size_t)RTOT * 128 + off);
            uint2 u3 = *(const uint2*)(g_pdh + 3 * (size_t)RTOT * 128 + off);
            float2 a0 = __half22float2(*(__half2*)&u0.x), a1 = __half22float2(*(__half2*)&u0.y);
            float2 b0 = __half22float2(*(__half2*)&u1.x), b1 = __half22float2(*(__half2*)&u1.y);
            float2 c0 = __half22float2(*(__half2*)&u2.x), c1 = __half22float2(*(__half2*)&u2.y);
            float2 d0 = __half22float2(*(__half2*)&u3.x), d1 = __half22float2(*(__half2*)&u3.y);
            v.x = fmaxf(w.x * a0.x + w.y * b0.x + w.z * c0.x + w.w * d0.x, 0.0f);
            v.y = fmaxf(w.x * a0.y + w.y * b0.y + w.z * c0.y + w.w * d0.y, 0.0f);
            v.z = fmaxf(w.x * a1.x + w.y * b1.x + w.z * c1.x + w.w * d1.x, 0.0f);
            v.w = fmaxf(w.x * a1.y + w.y * b1.y + w.z * c1.y + w.w * d1.y, 0.0f);
        } else {
            v = *(const float4*)(X + off);
        }
        *(float4*)&sX[row * XP + c4 * 4] = v;
    }

    // ---- W pipeline (register prefetch + smem double buffer) ----
    float wr[TN];
    auto ldg_W = [&](int f0) {
#pragma unroll
        for (int t = 0; t < TN; t++) {
            int idx = tid + t * 256;
            wr[t] = W[(size_t)(f0 + idx / FOUT) * FOUT + idx % FOUT];
        }
    };
    auto st_W = [&](int buf) {
#pragma unroll
        for (int t = 0; t < TN; t++) {
            int idx = tid + t * 256;
            sWb[(size_t)buf * 16 * (FOUT + 4) + (idx / FOUT) * (FOUT + 4) + idx % FOUT] = wr[t];
        }
    };

    float acc[4][TN];
#pragma unroll
    for (int r = 0; r < 4; r++)
#pragma unroll
        for (int c = 0; c < TN; c++) acc[r][c] = 0.0f;

    ldg_W(0);
    st_W(0);
    __syncthreads();   // covers Phase A stores + W buf 0

    for (int c8 = 0; c8 < 8; c8++) {
        if (c8 < 7) ldg_W((c8 + 1) * 16);
        const float* wbuf = sWb + (size_t)(c8 & 1) * 16 * (FOUT + 4);
        const float* x0 = &sX[(tr * 4 + 0) * XP + c8 * 16];
        const float* x1 = &sX[(tr * 4 + 1) * XP + c8 * 16];
        const float* x2 = &sX[(tr * 4 + 2) * XP + c8 * 16];
        const float* x3 = &sX[(tr * 4 + 3) * XP + c8 * 16];
#pragma unroll
        for (int k = 0; k < 16; k++) {
            float ra0 = x0[k], ra1 = x1[k], ra2 = x2[k], ra3 = x3[k];
            float rb[TN];
            if (TN == 8) {
                *(float4*)&rb[0] = *(const float4*)&wbuf[k * (FOUT + 4) + tc * 8];
                *(float4*)&rb[4] = *(const float4*)&wbuf[k * (FOUT + 4) + tc * 8 + 4];
            } else {
                *(float4*)&rb[0] = *(const float4*)&wbuf[k * (FOUT + 4) + tc * 4];
            }
#pragma unroll
            for (int c = 0; c < TN; c++) {
                acc[0][c] += ra0 * rb[c];
                acc[1][c] += ra1 * rb[c];
                acc[2][c] += ra2 * rb[c];
                acc[3][c] += ra3 * rb[c];
            }
        }
        if (c8 < 7) {
            st_W((c8 & 1) ^ 1);
            __syncthreads();
        }
    }

    // ---- stats partials (fp32 acc) ----
    float s1[4] = {0, 0, 0, 0}, s2[4] = {0, 0, 0, 0};
#pragma unroll
    for (int c = 0; c < TN; c++) {
        float av = __ldg(as + tc * TN + c);
        float dv = __ldg(ad + tc * TN + c);
#pragma unroll
        for (int r = 0; r < 4; r++) {
            s1[r] += acc[r][c] * av;
            s2[r] += acc[r][c] * dv;
        }
    }
    __syncthreads();   // X region dead; safe to alias sRed
#pragma unroll
    for (int r = 0; r < 4; r++) {
        sRed1[(tr * 4 + r) * 17 + tc] = s1[r];
        sRed2[(tr * 4 + r) * 17 + tc] = s2[r];
    }

    // transposed fp16 store (4 rows per thread)
#pragma unroll
    for (int c = 0; c < TN; c++) {
        int col = tc * TN + c;
        __half2 h01 = __float22half2_rn(make_float2(acc[0][c], acc[1][c]));
        __half2 h23 = __float22half2_rn(make_float2(acc[2][c], acc[3][c]));
        size_t off = (size_t)col * RTOT + row0 + tr * 4;
        *(__half2*)(Hh + off)     = h01;
        *(__half2*)(Hh + off + 2) = h23;
    }

    __syncthreads();
    if (tid < 64) {
        float t1 = 0.0f, t2 = 0.0f;
#pragma unroll
        for (int t = 0; t < 16; t++) { t1 += sRed1[tid * 17 + t]; t2 += sRed2[tid * 17 + t]; }
        int gr = row0 + tid;
        g_es[gr] = t1; g_r[gr] = __expf(-0.8f * t1);
        g_ed[gr] = t2; g_v[gr] = __expf(t2); g_q[gr] = __expf(0.2f * t2);
    }
}

// ---------------- fused masked-attention, B-resident, 16 warps --------------
// Block = (i-group of 512 rows) x (z-chunk of 512 j), 512 threads.
// Epilogue stores NORMALIZED partials d_z = D_z / s_z in fp16 (halved traffic).
template <int FOUT>
__global__ __launch_bounds__(512, 1) void attn_mma_kernel(
    const __half* __restrict__ Bh)
{
    constexpr int ROWB = 144;                    // P row stride (bytes)
    constexpr uint32_t PSZ = 128 * ROWB;         // one P tile (18432 B)
    constexpr uint32_t OFF_ES  = 0;              // 512 f32
    constexpr uint32_t OFF_R   = 2048;           // 512 f32
    constexpr uint32_t OFF_EDH = 4096;           // 512 half
    constexpr uint32_t OFF_VH  = 5120;           // 512 half
    constexpr uint32_t OFF_QH  = 6144;           // 512 half
    constexpr uint32_t OFF_P   = 7168;           // 2 x P tile
    constexpr uint32_t OFF_B   = OFF_P + 2 * PSZ;        // 44032
    constexpr uint32_t BUFSTRIDE = (uint32_t)FOUT * 128; // per fp16 tile
    constexpr uint32_t ONES  = 0x3C003C00u;      // fp16x2 {1,1}
    constexpr uint32_t CLAMP = 0x7B537B53u;      // fp16x2 {60000,60000}

    extern __shared__ char smem[];
    const uint32_t sb = smem_to_u32(smem);
    const int tid  = threadIdx.x;              // [0,512)
    const int wid  = tid >> 5;                 // [0,16)
    const int lane = tid & 31;
    const int grp  = wid >> 3;                 // warp-group 0/1
    const int wg   = wid & 7;                  // warp within group
    const int tig  = tid & 255;                // thread within group

    const int ig   = blockIdx.x;            // i-group (512 rows)
    const int b    = blockIdx.y;
    const int z    = blockIdx.z;
    const int base = b * NN;
    const int irow0 = ig * 512;              // node index of group start
    const int jbase = base + z * (JT_PER * 64);

    float*  ses  = (float*)(smem + OFF_ES);
    float*  sr   = (float*)(smem + OFF_R);
    __half* sedh = (__half*)(smem + OFF_EDH);
    __half* svh  = (__half*)(smem + OFF_VH);
    __half* sqh  = (__half*)(smem + OFF_QH);

    // ---- prologue staging (512 i-rows + 512 j-stats) ----
    {
        int i = base + irow0 + tid;
        ses[tid] = g_es[i];
        sr[tid]  = g_r[i];
        sedh[tid] = __float2half(g_ed[jbase + tid]);
        svh[tid]  = __float2half(fminf(g_v[jbase + tid], 60000.0f));
        sqh[tid]  = __float2half(g_q[jbase + tid]);
    }

    // ---- load ALL 8 B tiles once (cp.async, swizzled 128B rows) ----
    {
        constexpr int TOTCH = JT_PER * FOUT * 8;   // 16B chunks
#pragma unroll
        for (int t = 0; t < TOTCH / 512; t++) {
            int idx  = tid + t * 512;
            int tile = idx / (FOUT * 8);
            int rem  = idx % (FOUT * 8);
            int o = rem >> 3, c = rem & 7;
            uint32_t dst = sb + OFF_B + tile * BUFSTRIDE + o * 128
                         + (uint32_t)((c ^ (o & 7)) << 4);
            const char* src = (const char*)(Bh + (size_t)o * RTOT + jbase + tile * 64) + c * 16;
            CP_ASYNC16(dst, src);
        }
    }
    CP_COMMIT();

    // per-thread P-build coordinates (within group)
    const int iP = tig >> 1;                 // local row [0,128)
    const int jh = tig & 1;
    char* dstP = smem + OFF_P + grp * PSZ + iP * ROWB + jh * 64;

    // ldmatrix fixed addresses
    const int arow  = wg * 16 + (lane & 7) + (((lane >> 3) & 1) << 3);
    const int akoff = (lane >> 4) << 4;
    const uint32_t aBase = sb + OFF_P + grp * PSZ + arow * ROWB + akoff;
    const int brow = (lane & 7) + ((lane >> 4) << 3);
    const int bsel = (lane >> 3) & 1;

    constexpr int NT = FOUT / 8;

    CP_WAIT0();
    __syncthreads();   // B tiles + staging visible; ONLY block barrier

    for (int mm = 0; mm < 2; mm++) {
        const int m = grp * 2 + mm;          // i-tile index for this group
        const int iloc = m * 128;            // local row offset within group

        // per-thread row constants for this i-tile
        uint32_t es2, ri2;
        {
            __half eh = __float2half(ses[iloc + iP]);
            __half rh = __float2half(fminf(sr[iloc + iP], 60000.0f));
            uint16_t eu = __half_as_ushort(eh), ru = __half_as_ushort(rh);
            es2 = (uint32_t)eu | ((uint32_t)eu << 16);
            ri2 = (uint32_t)ru | ((uint32_t)ru << 16);
        }
        // mask words for this row, all 8 local j-tiles
        unsigned mw[JT_PER];
        {
            const unsigned* mrow = g_mask + (size_t)(irow0 + iloc + iP) * (NN / 32)
                                 + z * (JT_PER * 2) + jh;
#pragma unroll
            for (int l = 0; l < JT_PER; l++) mw[l] = mrow[l * 2];
        }

        float acc[NT][4];
#pragma unroll
        for (int n = 0; n < NT; n++)
#pragma unroll
            for (int q = 0; q < 4; q++) acc[n][q] = 0.0f;
        float accRS[4] = {0.f, 0.f, 0.f, 0.f};

        for (int l = 0; l < JT_PER; l++) {
            // build P rows (warp-local ownership), fp16x2 vectorized
            {
                const unsigned mm0 = mw[l];
                const __half* edl = sedh + l * 64 + (jh << 5);
                const __half* vl  = svh  + l * 64 + (jh << 5);
                const __half* ql  = sqh  + l * 64 + (jh << 5);
#pragma unroll
                for (int jj = 0; jj < 32; jj += 4) {
                    uint2 ed = *(const uint2*)(edl + jj);
                    uint2 vv = *(const uint2*)(vl + jj);
                    uint2 qq = *(const uint2*)(ql + jj);
                    uint32_t t0 = hadd2u(es2, ed.x);
                    uint32_t t1 = hadd2u(es2, ed.y);
                    uint32_t ge0 = hge2_mask(t0, 0u);
                    uint32_t ge1 = hge2_mask(t1, 0u);
                    uint32_t lo0 = hmul2u(ri2, qq.x);
                    uint32_t lo1 = hmul2u(ri2, qq.y);
                    uint32_t a0 = (vv.x & ge0) | (lo0 & ~ge0);
                    uint32_t a1 = (vv.y & ge1) | (lo1 & ~ge1);
                    uint32_t mb = mm0 >> jj;
                    a0 &= ((mb & 1u) * 0xFFFFu) | (((mb >> 1) & 1u) * 0xFFFF0000u);
                    a1 &= (((mb >> 2) & 1u) * 0xFFFFu) | (((mb >> 3) & 1u) * 0xFFFF0000u);
                    a0 = hmin2u(a0, CLAMP);
                    a1 = hmin2u(a1, CLAMP);
                    *(uint2*)(dstP + jj * 2) = make_uint2(a0, a1);
                }
            }
            __syncwarp();

            // MMA from resident B tile l
            const uint32_t bB = sb + OFF_B + l * BUFSTRIDE;
#pragma unroll
            for (int kk = 0; kk < 4; kk++) {
                uint32_t ah0, ah1, ah2, ah3;
                ldmx4(ah0, ah1, ah2, ah3, aBase + kk * 32);
                mma_f16(accRS, ah0, ah1, ah2, ah3, ONES, ONES);
                int cIdx = kk * 2 + bsel;
#pragma unroll
                for (int np = 0; np < NT / 2; np++) {
                    int r = np * 16 + brow;
                    uint32_t ba = bB + r * 128 + (uint32_t)((cIdx ^ (r & 7)) << 4);
                    uint32_t bh0, bh1, bh2, bh3;
                    ldmx4(bh0, bh1, bh2, bh3, ba);
                    mma_f16(acc[np * 2],     ah0, ah1, ah2, ah3, bh0, bh1);
                    mma_f16(acc[np * 2 + 1], ah0, ah1, ah2, ah3, bh2, bh3);
                }
            }
            __syncwarp();   // P reads done before next overwrite (warp-local)
        }

        // partial row sums (quad leader writes)
        if ((lane & 3) == 0) {
            int r0 = wg * 16 + (lane >> 2);
            g_ps[z * RTOT + base + irow0 + iloc + r0]     = accRS[0];
            g_ps[z * RTOT + base + irow0 + iloc + r0 + 8] = accRS[2];
        }

        // normalized fp16 partial D store: d = D / s
        {
            int r0 = wg * 16 + (lane >> 2);
            int r1 = r0 + 8;
            float inv0 = 1.0f / accRS[0];
            float inv1 = 1.0f / accRS[2];
            size_t rb = (size_t)z * RTOT * 128 + (size_t)(base + irow0 + iloc) * FOUT;
            __half* p0 = g_pdh + rb + (size_t)r0 * FOUT + (lane & 3) * 2;
            __half* p1 = g_pdh + rb + (size_t)r1 * FOUT + (lane & 3) * 2;
#pragma unroll
            for (int n = 0; n < NT; n++) {
                *(__half2*)(p0 + n * 8) = __float22half2_rn(
                    make_float2(acc[n][0] * inv0, acc[n][1] * inv0));
                *(__half2*)(p1 + n * 8) = __float22half2_rn(
                    make_float2(acc[n][2] * inv1, acc[n][3] * inv1));
            }
        }
    }
}

// ---------------- final linear (fused layer-3 combine) ----------------------
// X[b][k] = relu(sum_z w_z * d_z), staged once per block into smem.
__global__ __launch_bounds__(128) void final_partial_kernel(
    const float* __restrict__ Wlin)
{
    __shared__ float Xs[4096];       // 8 batches x 512 k
    __shared__ float4 sW4F[64];      // per-row z-weights
    const int c  = threadIdx.x;
    const int s  = blockIdx.x;
    const int k0 = s * 512;

    if (c < 64) {
        int bb = c >> 3, rr = c & 7;
        int rown = bb * NN + (k0 >> 6) + rr;
        float s0 = g_ps[rown], s1 = g_ps[RTOT + rown];
        float s2 = g_ps[2 * RTOT + rown], s3 = g_ps[3 * RTOT + rown];
        float inv = 1.0f / (s0 + s1 + s2 + s3);
        sW4F[c] = make_float4(s0 * inv, s1 * inv, s2 * inv, s3 * inv);
    }
    __syncthreads();

#pragma unroll
    for (int t = 0; t < 8; t++) {
        int idx = (c + t * 128) * 4;       // 4-elem granularity, 0..4095
        int bb  = idx >> 9;
        int kk  = idx & 511;
        size_t off = (size_t)bb * 131072 + k0 + kk;
        float4 w = sW4F[(bb << 3) + (kk >> 6)];
        uint2 u0 = *(const uint2*)(g_pdh + off);
        uint2 u1 = *(const uint2*)(g_pdh + (size_t)RTOT * 128 + off);
        uint2 u2 = *(const uint2*)(g_pdh + 2 * (size_t)RTOT * 128 + off);
        uint2 u3 = *(const uint2*)(g_pdh + 3 * (size_t)RTOT * 128 + off);
        float2 a0 = __half22float2(*(__half2*)&u0.x), a1 = __half22float2(*(__half2*)&u0.y);
        float2 b0 = __half22float2(*(__half2*)&u1.x), b1 = __half22float2(*(__half2*)&u1.y);
        float2 c0 = __half22float2(*(__half2*)&u2.x), c1 = __half22float2(*(__half2*)&u2.y);
        float2 d0 = __half22float2(*(__half2*)&u3.x), d1 = __half22float2(*(__half2*)&u3.y);
        float4 v;
        v.x = fmaxf(w.x * a0.x + w.y * b0.x + w.z * c0.x + w.w * d0.x, 0.0f);
        v.y = fmaxf(w.x * a0.y + w.y * b0.y + w.z * c0.y + w.w * d0.y, 0.0f);
        v.z = fmaxf(w.x * a1.x + w.y * b1.x + w.z * c1.x + w.w * d1.x, 0.0f);
        v.w = fmaxf(w.x * a1.y + w.y * b1.y + w.z * c1.y + w.w * d1.y, 0.0f);
        *(float4*)&Xs[idx] = v;
    }
    __syncthreads();

    float acc[8] = {0, 0, 0, 0, 0, 0, 0, 0};
    for (int kk = 0; kk < 512; kk++) {
        float w = Wlin[(size_t)(k0 + kk) * 128 + c];
#pragma unroll
        for (int bb = 0; bb < 8; bb++) acc[bb] += Xs[bb * 512 + kk] * w;
    }
#pragma unroll
    for (int bb = 0; bb < 8; bb++) g_part[s * 1024 + bb * 128 + c] = acc[bb];
}

__global__ __launch_bounds__(256) void final_reduce_kernel(
    const float* __restrict__ blin, float* __restrict__ out)
{
    int idx = blockIdx.x * 256 + threadIdx.x;
    if (idx < 1024) {
        float s = 0.0f;
        for (int sp = 0; sp < 256; sp++) s += g_part[sp * 1024 + idx];
        out[idx] = s + blin[idx & 127];
    }
}

// ---------------- host driver ------------------------------------------------
extern "C" void kernel_launch(void* const* d_in, const int* in_sizes, int n_in,
                              void* d_out, int out_size)
{
    const float* x    = (const float*)d_in[0];
    const float* adj  = (const float*)d_in[1];
    const float* W1   = (const float*)d_in[2];
    const float* a1s  = (const float*)d_in[3];
    const float* a1d  = (const float*)d_in[4];
    const float* W2   = (const float*)d_in[5];
    const float* a2s  = (const float*)d_in[6];
    const float* a2d  = (const float*)d_in[7];
    const float* W3   = (const float*)d_in[8];
    const float* a3s  = (const float*)d_in[9];
    const float* a3d  = (const float*)d_in[10];
    const float* Wlin = (const float*)d_in[11];
    const float* blin = (const float*)d_in[12];

    void* phh; cudaGetSymbolAddress(&phh, g_hh);
    __half* hh = (__half*)phh;

    constexpr int SM128 = 44032 + 8 * 128 * 128;  // attn 175104
    constexpr int SM64  = 44032 + 8 * 64 * 128;   // attn 109568
    cudaFuncSetAttribute(attn_mma_kernel<128>, cudaFuncAttributeMaxDynamicSharedMemorySize, SM128);
    cudaFuncSetAttribute(attn_mma_kernel<64>,  cudaFuncAttributeMaxDynamicSharedMemorySize, SM64);

    // sgemm dynamic smem: X(33792) + W(2*16*(FOUT+4)*4) + sWz(64*16)
    constexpr int SG128 = 64 * 132 * 4 + 2 * 16 * 132 * 4 + 1024;  // 51712
    constexpr int SG64  = 64 * 132 * 4 + 2 * 16 * 68 * 4 + 1024;   // 43520
    cudaFuncSetAttribute(sgemm_h_kernel<128, 0>, cudaFuncAttributeMaxDynamicSharedMemorySize, SG128);
    cudaFuncSetAttribute(sgemm_h_kernel<128, 1>, cudaFuncAttributeMaxDynamicSharedMemorySize, SG128);
    cudaFuncSetAttribute(sgemm_h_kernel<64, 1>,  cudaFuncAttributeMaxDynamicSharedMemorySize, SG64);

    build_mask_kernel<<<16384, 256>>>(adj);

    // layer 1 (128 -> 128): reads x directly
    sgemm_h_kernel<128, 0><<<256, 256, SG128>>>(x, W1, a1s, a1d, hh);
    attn_mma_kernel<128><<<dim3(IGROUPS, 8, ZSPLIT), 512, SM128>>>(hh);

    // layer 2 (128 -> 128): reads fused layer-1 fp16 partials
    sgemm_h_kernel<128, 1><<<256, 256, SG128>>>(nullptr, W2, a2s, a2d, hh);
    attn_mma_kernel<128><<<dim3(IGROUPS, 8, ZSPLIT), 512, SM128>>>(hh);

    // layer 3 (128 -> 64): reads fused layer-2 fp16 partials
    sgemm_h_kernel<64, 1><<<256, 256, SG64>>>(nullptr, W3, a3s, a3d, hh);
    attn_mma_kernel<64><<<dim3(IGROUPS, 8, ZSPLIT), 512, SM64>>>(hh);

    // final linear (fused layer-3 combine)
    final_partial_kernel<<<256, 128>>>(Wlin);
    final_reduce_kernel<<<4, 256>>>(blin, (float*)d_out);
}

// round 17
// speedup vs baseline: 1.1802x; 1.1344x over previous
#include <cuda_runtime.h>
#include <cuda_fp16.h>
#include <cstdint>

// Problem constants (GATAuto: B=8, N=2048, Fin=128, H=[128,128,64], C=128)
#define BB 8
#define NN 2048
#define RTOT (BB*NN)          // 16384 rows
#define ZSPLIT 4
#define JT_PER ((NN/64)/ZSPLIT)   // 8 j-tiles per z-chunk
#define IGROUPS 4                 // i-groups of 512 rows

// ---------------- scratch (device globals; no allocation allowed) ----------
__device__ __align__(16) __half g_hh[128 * RTOT];          // h transposed fp16 [o][row]
__device__ __align__(16) __half g_pdh[(size_t)ZSPLIT * RTOT * 128];  // normalized partial D (fp16)
__device__ float    g_ps[ZSPLIT * RTOT];                   // partial row sums
__device__ float    g_es[RTOT], g_r[RTOT];                 // es, exp(-0.8 es)
__device__ float    g_ed[RTOT], g_v[RTOT], g_q[RTOT];      // ed, exp(ed), exp(0.2 ed)
__device__ unsigned g_mask[NN * (NN / 32)];                // adjacency bitmask, 512KB
__device__ float    g_part[256 * 1024];                    // final-linear split-K partials

// ======================= warp MMA helpers (baseline PTX) =====================
__device__ __forceinline__ uint32_t smem_to_u32(const void* p) {
    uint32_t a;
    asm("{ .reg .u64 t; cvta.to.shared.u64 t, %1; cvt.u32.u64 %0, t; }" : "=r"(a) : "l"(p));
    return a;
}
__device__ __forceinline__ void ldmx4(uint32_t& r0, uint32_t& r1, uint32_t& r2, uint32_t& r3,
                                      uint32_t addr) {
    asm volatile("ldmatrix.sync.aligned.m8n8.x4.shared.b16 {%0,%1,%2,%3}, [%4];"
                 : "=r"(r0), "=r"(r1), "=r"(r2), "=r"(r3) : "r"(addr));
}
__device__ __forceinline__ void mma_f16(float* d, uint32_t a0, uint32_t a1, uint32_t a2,
                                        uint32_t a3, uint32_t b0, uint32_t b1) {
    asm volatile("mma.sync.aligned.m16n8k16.row.col.f32.f16.f16.f32 "
                 "{%0,%1,%2,%3}, {%4,%5,%6,%7}, {%8,%9}, {%0,%1,%2,%3};"
                 : "+f"(d[0]), "+f"(d[1]), "+f"(d[2]), "+f"(d[3])
                 : "r"(a0), "r"(a1), "r"(a2), "r"(a3), "r"(b0), "r"(b1));
}
#define CP_ASYNC16(dst, src) \
    asm volatile("cp.async.ca.shared.global [%0], [%1], 16;" :: "r"(dst), "l"(src))
#define CP_COMMIT() asm volatile("cp.async.commit_group;" ::: "memory")
#define CP_WAIT0()  asm volatile("cp.async.wait_group 0;" ::: "memory")

// fp16x2 packed ops on u32 registers
__device__ __forceinline__ uint32_t hadd2u(uint32_t a, uint32_t b) {
    uint32_t d; asm("add.f16x2 %0, %1, %2;" : "=r"(d) : "r"(a), "r"(b)); return d;
}
__device__ __forceinline__ uint32_t hmul2u(uint32_t a, uint32_t b) {
    uint32_t d; asm("mul.f16x2 %0, %1, %2;" : "=r"(d) : "r"(a), "r"(b)); return d;
}
__device__ __forceinline__ uint32_t hmin2u(uint32_t a, uint32_t b) {
    uint32_t d; asm("min.f16x2 %0, %1, %2;" : "=r"(d) : "r"(a), "r"(b)); return d;
}
__device__ __forceinline__ uint32_t hge2_mask(uint32_t a, uint32_t b) {
    uint32_t d; asm("set.ge.u32.f16x2 %0, %1, %2;" : "=r"(d) : "r"(a), "r"(b)); return d;
}

// ---------------- adjacency bitmask ----------------------------------------
__global__ void build_mask_kernel(const float* __restrict__ adj) {
    int w    = blockIdx.x * 8 + (threadIdx.x >> 5);
    int lane = threadIdx.x & 31;
    int row  = w >> 6;
    int wc   = w & 63;
    float av = adj[(size_t)row * NN + wc * 32 + lane];
    unsigned m = __ballot_sync(0xffffffffu, av > 0.0f);
    if (lane == 0) g_mask[w] = m;
}

// ---------------- h = X @ W via split-fp16 MMA + fused stats ----------------
// Block = 128 rows, 256 threads (8 warps, warp owns 16 rows). Grid 128.
// X split hi/lo fp16; W transposed + split hi/lo fp16.
// D = Xhi@Whi + Xhi@Wlo + Xlo@Whi (fp32 accum, ~fp32 precision).
// FUSE=1: X = relu(sum_z w_z * d_z) from fp16 normalized partials.
template <int FOUT, int FUSE>
__global__ __launch_bounds__(256) void sgemm_mma_kernel(
    const float* __restrict__ X, const float* __restrict__ W,
    const float* __restrict__ as, const float* __restrict__ ad,
    __half* __restrict__ Hh)
{
    constexpr int NT = FOUT / 8;
    constexpr int ROWB = 144;                         // padded row (bytes)
    constexpr uint32_t TSZ = 128 * ROWB;              // X tile (per hl,half)
    constexpr uint32_t WSZ = (uint32_t)FOUT * ROWB;   // W tile
    constexpr uint32_t OFF_WZ = 0;                    // 128 float4
    constexpr uint32_t OFF_X  = 2048;                 // tiles: [hi h0, hi h1, lo h0, lo h1]
    constexpr uint32_t OFF_W  = OFF_X + 4 * TSZ;
    constexpr int HDP = FOUT + 1;                     // hD padded stride (floats)

    extern __shared__ char smem[];
    const uint32_t sb = smem_to_u32(smem);
    float4* sWz = (float4*)(smem + OFF_WZ);
    float*  hD  = (float*)(smem + OFF_X);             // alias X tiles post-MMA

    const int tid  = threadIdx.x;
    const int wid  = tid >> 5;
    const int lane = tid & 31;
    const int row0 = blockIdx.x * 128;

    if (FUSE) {
        if (tid < 128) {
            int gr = row0 + tid;
            float s0 = g_ps[gr], s1 = g_ps[RTOT + gr];
            float s2 = g_ps[2 * RTOT + gr], s3 = g_ps[3 * RTOT + gr];
            float inv = 1.0f / (s0 + s1 + s2 + s3);
            sWz[tid] = make_float4(s0 * inv, s1 * inv, s2 * inv, s3 * inv);
        }
        __syncthreads();
    }

    // ---- stage X hi/lo (4-element chunks; fused combine if FUSE) ----
#pragma unroll
    for (int t = 0; t < 16; t++) {
        int idx = tid + t * 256;       // 4096 chunks
        int row = idx >> 5;
        int q   = idx & 31;            // 4-elem chunk within row
        size_t off = (size_t)(row0 + row) * 128 + q * 4;
        float xv0, xv1, xv2, xv3;
        if (FUSE) {
            float4 w = sWz[row];
            uint2 u0 = *(const uint2*)(g_pdh + off);
            uint2 u1 = *(const uint2*)(g_pdh + (size_t)RTOT * 128 + off);
            uint2 u2 = *(const uint2*)(g_pdh + 2 * (size_t)RTOT * 128 + off);
            uint2 u3 = *(const uint2*)(g_pdh + 3 * (size_t)RTOT * 128 + off);
            float2 a0 = __half22float2(*(__half2*)&u0.x), a1 = __half22float2(*(__half2*)&u0.y);
            float2 b0 = __half22float2(*(__half2*)&u1.x), b1 = __half22float2(*(__half2*)&u1.y);
            float2 c0 = __half22float2(*(__half2*)&u2.x), c1 = __half22float2(*(__half2*)&u2.y);
            float2 d0 = __half22float2(*(__half2*)&u3.x), d1 = __half22float2(*(__half2*)&u3.y);
            xv0 = fmaxf(w.x * a0.x + w.y * b0.x + w.z * c0.x + w.w * d0.x, 0.0f);
            xv1 = fmaxf(w.x * a0.y + w.y * b0.y + w.z * c0.y + w.w * d0.y, 0.0f);
            xv2 = fmaxf(w.x * a1.x + w.y * b1.x + w.z * c1.x + w.w * d1.x, 0.0f);
            xv3 = fmaxf(w.x * a1.y + w.y * b1.y + w.z * c1.y + w.w * d1.y, 0.0f);
        } else {
            float4 v = *(const float4*)(X + off);
            xv0 = v.x; xv1 = v.y; xv2 = v.z; xv3 = v.w;
        }
        __half2 h01 = __float22half2_rn(make_float2(xv0, xv1));
        __half2 h23 = __float22half2_rn(make_float2(xv2, xv3));
        float2 f01 = __half22float2(h01), f23 = __half22float2(h23);
        __half2 l01 = __float22half2_rn(make_float2(xv0 - f01.x, xv1 - f01.y));
        __half2 l23 = __float22half2_rn(make_float2(xv2 - f23.x, xv3 - f23.y));
        int half_ = q >> 4;                        // which 64-k half
        uint32_t xb = (uint32_t)(row * ROWB + (q & 15) * 8);
        *(uint2*)(smem + OFF_X + half_ * TSZ + xb)        = make_uint2(*(uint32_t*)&h01, *(uint32_t*)&h23);
        *(uint2*)(smem + OFF_X + (2 + half_) * TSZ + xb)  = make_uint2(*(uint32_t*)&l01, *(uint32_t*)&l23);
    }

    // ---- stage W transposed hi/lo ----
#pragma unroll
    for (int t = 0; t < FOUT / 2; t++) {
        int idx = tid + t * 256;          // 128*FOUT elements
        int k = idx / FOUT, o = idx % FOUT;
        float w = W[idx];
        __half whi = __float2half(w);
        __half wlo = __float2half(w - __half2float(whi));
        int half_ = k >> 6;
        uint32_t wb = (uint32_t)(o * ROWB + (k & 63) * 2);
        *(__half*)(smem + OFF_W + half_ * WSZ + wb)       = whi;
        *(__half*)(smem + OFF_W + (2 + half_) * WSZ + wb) = wlo;
    }
    __syncthreads();

    // ---- MMA mainloop ----
    const int arow  = wid * 16 + (lane & 7) + (((lane >> 3) & 1) << 3);
    const int akoff = (lane >> 4) << 4;
    const int brow  = (lane & 7) + ((lane >> 4) << 3);
    const int bsel  = (lane >> 3) & 1;

    float acc[NT][4];
#pragma unroll
    for (int n = 0; n < NT; n++)
#pragma unroll
        for (int q = 0; q < 4; q++) acc[n][q] = 0.0f;

#pragma unroll
    for (int half_ = 0; half_ < 2; half_++) {
        const uint32_t aHi = sb + OFF_X + half_ * TSZ + arow * ROWB + akoff;
        const uint32_t aLo = sb + OFF_X + (2 + half_) * TSZ + arow * ROWB + akoff;
        const uint32_t bHiB = sb + OFF_W + half_ * WSZ;
        const uint32_t bLoB = sb + OFF_W + (2 + half_) * WSZ;
#pragma unroll
        for (int kk = 0; kk < 4; kk++) {
            uint32_t ah0, ah1, ah2, ah3, al0, al1, al2, al3;
            ldmx4(ah0, ah1, ah2, ah3, aHi + kk * 32);
            ldmx4(al0, al1, al2, al3, aLo + kk * 32);
            int cIdx = kk * 2 + bsel;
#pragma unroll
            for (int np = 0; np < NT / 2; np++) {
                int r = np * 16 + brow;
                uint32_t bo = (uint32_t)(r * ROWB + cIdx * 16);
                uint32_t bh0, bh1, bh2, bh3, bl0, bl1, bl2, bl3;
                ldmx4(bh0, bh1, bh2, bh3, bHiB + bo);
                ldmx4(bl0, bl1, bl2, bl3, bLoB + bo);
                mma_f16(acc[np * 2],     ah0, ah1, ah2, ah3, bh0, bh1);
                mma_f16(acc[np * 2],     ah0, ah1, ah2, ah3, bl0, bl1);
                mma_f16(acc[np * 2],     al0, al1, al2, al3, bh0, bh1);
                mma_f16(acc[np * 2 + 1], ah0, ah1, ah2, ah3, bh2, bh3);
                mma_f16(acc[np * 2 + 1], ah0, ah1, ah2, ah3, bl2, bl3);
                mma_f16(acc[np * 2 + 1], al0, al1, al2, al3, bh2, bh3);
            }
        }
    }
    __syncthreads();   // tiles dead; hD aliases X region

    // ---- dump D to smem [row][FOUT+1] ----
    {
        int r0 = wid * 16 + (lane >> 2);
        int r1 = r0 + 8;
#pragma unroll
        for (int n = 0; n < NT; n++) {
            int c = n * 8 + (lane & 3) * 2;
            hD[r0 * HDP + c]     = acc[n][0];
            hD[r0 * HDP + c + 1] = acc[n][1];
            hD[r1 * HDP + c]     = acc[n][2];
            hD[r1 * HDP + c + 1] = acc[n][3];
        }
    }
    __syncthreads();

    // ---- stats: es/ed + exp factors ----
    {
        int row = tid >> 1, hf = tid & 1;
        const float* hr = hD + row * HDP + hf * (FOUT / 2);
        const float* asp = as + hf * (FOUT / 2);
        const float* adp = ad + hf * (FOUT / 2);
        float s1 = 0.0f, s2 = 0.0f;
#pragma unroll
        for (int o = 0; o < FOUT / 2; o++) {
            float v = hr[o];
            s1 += v * __ldg(asp + o);
            s2 += v * __ldg(adp + o);
        }
        s1 += __shfl_xor_sync(0xffffffffu, s1, 1);
        s2 += __shfl_xor_sync(0xffffffffu, s2, 1);
        if (hf == 0) {
            int gr = row0 + row;
            g_es[gr] = s1; g_r[gr] = __expf(-0.8f * s1);
            g_ed[gr] = s2; g_v[gr] = __expf(s2); g_q[gr] = __expf(0.2f * s2);
        }
    }

    // ---- transposed fp16 h store: Hh[col][row] ----
#pragma unroll
    for (int t = 0; t < (128 * FOUT / 2) / 256; t++) {
        int idx = tid + t * 256;
        int col = idx >> 6;                  // 64 row-pairs per col
        int rp  = idx & 63;
        float v0 = hD[(2 * rp) * HDP + col];
        float v1 = hD[(2 * rp + 1) * HDP + col];
        *(__half2*)(Hh + (size_t)col * RTOT + row0 + 2 * rp) =
            __float22half2_rn(make_float2(v0, v1));
    }
}

// ---------------- fused masked-attention, B-resident, 16 warps --------------
// Block = (i-group of 512 rows) x (z-chunk of 512 j), 512 threads.
// Epilogue stores NORMALIZED partials d_z = D_z / s_z in fp16 (halved traffic).
template <int FOUT>
__global__ __launch_bounds__(512, 1) void attn_mma_kernel(
    const __half* __restrict__ Bh)
{
    constexpr int ROWB = 144;                    // P row stride (bytes)
    constexpr uint32_t PSZ = 128 * ROWB;         // one P tile (18432 B)
    constexpr uint32_t OFF_ES  = 0;              // 512 f32
    constexpr uint32_t OFF_R   = 2048;           // 512 f32
    constexpr uint32_t OFF_EDH = 4096;           // 512 half
    constexpr uint32_t OFF_VH  = 5120;           // 512 half
    constexpr uint32_t OFF_QH  = 6144;           // 512 half
    constexpr uint32_t OFF_P   = 7168;           // 2 x P tile
    constexpr uint32_t OFF_B   = OFF_P + 2 * PSZ;        // 44032
    constexpr uint32_t BUFSTRIDE = (uint32_t)FOUT * 128; // per fp16 tile
    constexpr uint32_t ONES  = 0x3C003C00u;      // fp16x2 {1,1}
    constexpr uint32_t CLAMP = 0x7B537B53u;      // fp16x2 {60000,60000}

    extern __shared__ char smem[];
    const uint32_t sb = smem_to_u32(smem);
    const int tid  = threadIdx.x;              // [0,512)
    const int wid  = tid >> 5;                 // [0,16)
    const int lane = tid & 31;
    const int grp  = wid >> 3;                 // warp-group 0/1
    const int wg   = wid & 7;                  // warp within group
    const int tig  = tid & 255;                // thread within group

    const int ig   = blockIdx.x;            // i-group (512 rows)
    const int b    = blockIdx.y;
    const int z    = blockIdx.z;
    const int base = b * NN;
    const int irow0 = ig * 512;              // node index of group start
    const int jbase = base + z * (JT_PER * 64);

    float*  ses  = (float*)(smem + OFF_ES);
    float*  sr   = (float*)(smem + OFF_R);
    __half* sedh = (__half*)(smem + OFF_EDH);
    __half* svh  = (__half*)(smem + OFF_VH);
    __half* sqh  = (__half*)(smem + OFF_QH);

    // ---- prologue staging (512 i-rows + 512 j-stats) ----
    {
        int i = base + irow0 + tid;
        ses[tid] = g_es[i];
        sr[tid]  = g_r[i];
        sedh[tid] = __float2half(g_ed[jbase + tid]);
        svh[tid]  = __float2half(fminf(g_v[jbase + tid], 60000.0f));
        sqh[tid]  = __float2half(g_q[jbase + tid]);
    }

    // ---- load ALL 8 B tiles once (cp.async, swizzled 128B rows) ----
    {
        constexpr int TOTCH = JT_PER * FOUT * 8;   // 16B chunks
#pragma unroll
        for (int t = 0; t < TOTCH / 512; t++) {
            int idx  = tid + t * 512;
            int tile = idx / (FOUT * 8);
            int rem  = idx % (FOUT * 8);
            int o = rem >> 3, c = rem & 7;
            uint32_t dst = sb + OFF_B + tile * BUFSTRIDE + o * 128
                         + (uint32_t)((c ^ (o & 7)) << 4);
            const char* src = (const char*)(Bh + (size_t)o * RTOT + jbase + tile * 64) + c * 16;
            CP_ASYNC16(dst, src);
        }
    }
    CP_COMMIT();

    // per-thread P-build coordinates (within group)
    const int iP = tig >> 1;                 // local row [0,128)
    const int jh = tig & 1;
    char* dstP = smem + OFF_P + grp * PSZ + iP * ROWB + jh * 64;

    // ldmatrix fixed addresses
    const int arow  = wg * 16 + (lane & 7) + (((lane >> 3) & 1) << 3);
    const int akoff = (lane >> 4) << 4;
    const uint32_t aBase = sb + OFF_P + grp * PSZ + arow * ROWB + akoff;
    const int brow = (lane & 7) + ((lane >> 4) << 3);
    const int bsel = (lane >> 3) & 1;

    constexpr int NT = FOUT / 8;

    CP_WAIT0();
    __syncthreads();   // B tiles + staging visible; ONLY block barrier

    for (int mm = 0; mm < 2; mm++) {
        const int m = grp * 2 + mm;          // i-tile index for this group
        const int iloc = m * 128;            // local row offset within group

        // per-thread row constants for this i-tile
        uint32_t es2, ri2;
        {
            __half eh = __float2half(ses[iloc + iP]);
            __half rh = __float2half(fminf(sr[iloc + iP], 60000.0f));
            uint16_t eu = __half_as_ushort(eh), ru = __half_as_ushort(rh);
            es2 = (uint32_t)eu | ((uint32_t)eu << 16);
            ri2 = (uint32_t)ru | ((uint32_t)ru << 16);
        }
        // mask words for this row, all 8 local j-tiles
        unsigned mw[JT_PER];
        {
            const unsigned* mrow = g_mask + (size_t)(irow0 + iloc + iP) * (NN / 32)
                                 + z * (JT_PER * 2) + jh;
#pragma unroll
            for (int l = 0; l < JT_PER; l++) mw[l] = mrow[l * 2];
        }

        float acc[NT][4];
#pragma unroll
        for (int n = 0; n < NT; n++)
#pragma unroll
            for (int q = 0; q < 4; q++) acc[n][q] = 0.0f;
        float accRS[4] = {0.f, 0.f, 0.f, 0.f};

        for (int l = 0; l < JT_PER; l++) {
            // build P rows (warp-local ownership), fp16x2 vectorized
            {
                const unsigned mm0 = mw[l];
                const __half* edl = sedh + l * 64 + (jh << 5);
                const __half* vl  = svh  + l * 64 + (jh << 5);
                const __half* ql  = sqh  + l * 64 + (jh << 5);
#pragma unroll
                for (int jj = 0; jj < 32; jj += 4) {
                    uint2 ed = *(const uint2*)(edl + jj);
                    uint2 vv = *(const uint2*)(vl + jj);
                    uint2 qq = *(const uint2*)(ql + jj);
                    uint32_t t0 = hadd2u(es2, ed.x);
                    uint32_t t1 = hadd2u(es2, ed.y);
                    uint32_t ge0 = hge2_mask(t0, 0u);
                    uint32_t ge1 = hge2_mask(t1, 0u);
                    uint32_t lo0 = hmul2u(ri2, qq.x);
                    uint32_t lo1 = hmul2u(ri2, qq.y);
                    uint32_t a0 = (vv.x & ge0) | (lo0 & ~ge0);
                    uint32_t a1 = (vv.y & ge1) | (lo1 & ~ge1);
                    uint32_t mb = mm0 >> jj;
                    a0 &= ((mb & 1u) * 0xFFFFu) | (((mb >> 1) & 1u) * 0xFFFF0000u);
                    a1 &= (((mb >> 2) & 1u) * 0xFFFFu) | (((mb >> 3) & 1u) * 0xFFFF0000u);
                    a0 = hmin2u(a0, CLAMP);
                    a1 = hmin2u(a1, CLAMP);
                    *(uint2*)(dstP + jj * 2) = make_uint2(a0, a1);
                }
            }
            __syncwarp();

            // MMA from resident B tile l
            const uint32_t bB = sb + OFF_B + l * BUFSTRIDE;
#pragma unroll
            for (int kk = 0; kk < 4; kk++) {
                uint32_t ah0, ah1, ah2, ah3;
                ldmx4(ah0, ah1, ah2, ah3, aBase + kk * 32);
                mma_f16(accRS, ah0, ah1, ah2, ah3, ONES, ONES);
                int cIdx = kk * 2 + bsel;
#pragma unroll
                for (int np = 0; np < NT / 2; np++) {
                    int r = np * 16 + brow;
                    uint32_t ba = bB + r * 128 + (uint32_t)((cIdx ^ (r & 7)) << 4);
                    uint32_t bh0, bh1, bh2, bh3;
                    ldmx4(bh0, bh1, bh2, bh3, ba);
                    mma_f16(acc[np * 2],     ah0, ah1, ah2, ah3, bh0, bh1);
                    mma_f16(acc[np * 2 + 1], ah0, ah1, ah2, ah3, bh2, bh3);
                }
            }
            __syncwarp();   // P reads done before next overwrite (warp-local)
        }

        // partial row sums (quad leader writes)
        if ((lane & 3) == 0) {
            int r0 = wg * 16 + (lane >> 2);
            g_ps[z * RTOT + base + irow0 + iloc + r0]     = accRS[0];
            g_ps[z * RTOT + base + irow0 + iloc + r0 + 8] = accRS[2];
        }

        // normalized fp16 partial D store: d = D / s
        {
            int r0 = wg * 16 + (lane >> 2);
            int r1 = r0 + 8;
            float inv0 = 1.0f / accRS[0];
            float inv1 = 1.0f / accRS[2];
            size_t rb = (size_t)z * RTOT * 128 + (size_t)(base + irow0 + iloc) * FOUT;
            __half* p0 = g_pdh + rb + (size_t)r0 * FOUT + (lane & 3) * 2;
            __half* p1 = g_pdh + rb + (size_t)r1 * FOUT + (lane & 3) * 2;
#pragma unroll
            for (int n = 0; n < NT; n++) {
                *(__half2*)(p0 + n * 8) = __float22half2_rn(
                    make_float2(acc[n][0] * inv0, acc[n][1] * inv0));
                *(__half2*)(p1 + n * 8) = __float22half2_rn(
                    make_float2(acc[n][2] * inv1, acc[n][3] * inv1));
            }
        }
    }
}

// ---------------- final linear (fused layer-3 combine) ----------------------
// X[b][k] = relu(sum_z w_z * d_z), staged once per block into smem.
__global__ __launch_bounds__(128) void final_partial_kernel(
    const float* __restrict__ Wlin)
{
    __shared__ float Xs[4096];       // 8 batches x 512 k
    __shared__ float4 sW4F[64];      // per-row z-weights
    const int c  = threadIdx.x;
    const int s  = blockIdx.x;
    const int k0 = s * 512;

    if (c < 64) {
        int bb = c >> 3, rr = c & 7;
        int rown = bb * NN + (k0 >> 6) + rr;
        float s0 = g_ps[rown], s1 = g_ps[RTOT + rown];
        float s2 = g_ps[2 * RTOT + rown], s3 = g_ps[3 * RTOT + rown];
        float inv = 1.0f / (s0 + s1 + s2 + s3);
        sW4F[c] = make_float4(s0 * inv, s1 * inv, s2 * inv, s3 * inv);
    }
    __syncthreads();

#pragma unroll
    for (int t = 0; t < 8; t++) {
        int idx = (c + t * 128) * 4;       // 4-elem granularity, 0..4095
        int bb  = idx >> 9;
        int kk  = idx & 511;
        size_t off = (size_t)bb * 131072 + k0 + kk;
        float4 w = sW4F[(bb << 3) + (kk >> 6)];
        uint2 u0 = *(const uint2*)(g_pdh + off);
        uint2 u1 = *(const uint2*)(g_pdh + (size_t)RTOT * 128 + off);
        uint2 u2 = *(const uint2*)(g_pdh + 2 * (size_t)RTOT * 128 + off);
        uint2 u3 = *(const uint2*)(g_pdh + 3 * (size_t)RTOT * 128 + off);
        float2 a0 = __half22float2(*(__half2*)&u0.x), a1 = __half22float2(*(__half2*)&u0.y);
        float2 b0 = __half22float2(*(__half2*)&u1.x), b1 = __half22float2(*(__half2*)&u1.y);
        float2 c0 = __half22float2(*(__half2*)&u2.x), c1 = __half22float2(*(__half2*)&u2.y);
        float2 d0 = __half22float2(*(__half2*)&u3.x), d1 = __half22float2(*(__half2*)&u3.y);
        float4 v;
        v.x = fmaxf(w.x * a0.x + w.y * b0.x + w.z * c0.x + w.w * d0.x, 0.0f);
        v.y = fmaxf(w.x * a0.y + w.y * b0.y + w.z * c0.y + w.w * d0.y, 0.0f);
        v.z = fmaxf(w.x * a1.x + w.y * b1.x + w.z * c1.x + w.w * d1.x, 0.0f);
        v.w = fmaxf(w.x * a1.y + w.y * b1.y + w.z * c1.y + w.w * d1.y, 0.0f);
        *(float4*)&Xs[idx] = v;
    }
    __syncthreads();

    float acc[8] = {0, 0, 0, 0, 0, 0, 0, 0};
    for (int kk = 0; kk < 512; kk++) {
        float w = Wlin[(size_t)(k0 + kk) * 128 + c];
#pragma unroll
        for (int bb = 0; bb < 8; bb++) acc[bb] += Xs[bb * 512 + kk] * w;
    }
#pragma unroll
    for (int bb = 0; bb < 8; bb++) g_part[s * 1024 + bb * 128 + c] = acc[bb];
}

__global__ __launch_bounds__(256) void final_reduce_kernel(
    const float* __restrict__ blin, float* __restrict__ out)
{
    int idx = blockIdx.x * 256 + threadIdx.x;
    if (idx < 1024) {
        float s = 0.0f;
        for (int sp = 0; sp < 256; sp++) s += g_part[sp * 1024 + idx];
        out[idx] = s + blin[idx & 127];
    }
}

// ---------------- host driver ------------------------------------------------
extern "C" void kernel_launch(void* const* d_in, const int* in_sizes, int n_in,
                              void* d_out, int out_size)
{
    const float* x    = (const float*)d_in[0];
    const float* adj  = (const float*)d_in[1];
    const float* W1   = (const float*)d_in[2];
    const float* a1s  = (const float*)d_in[3];
    const float* a1d  = (const float*)d_in[4];
    const float* W2   = (const float*)d_in[5];
    const float* a2s  = (const float*)d_in[6];
    const float* a2d  = (const float*)d_in[7];
    const float* W3   = (const float*)d_in[8];
    const float* a3s  = (const float*)d_in[9];
    const float* a3d  = (const float*)d_in[10];
    const float* Wlin = (const float*)d_in[11];
    const float* blin = (const float*)d_in[12];

    void* phh; cudaGetSymbolAddress(&phh, g_hh);
    __half* hh = (__half*)phh;

    constexpr int SM128 = 44032 + 8 * 128 * 128;  // attn 175104
    constexpr int SM64  = 44032 + 8 * 64 * 128;   // attn 109568
    cudaFuncSetAttribute(attn_mma_kernel<128>, cudaFuncAttributeMaxDynamicSharedMemorySize, SM128);
    cudaFuncSetAttribute(attn_mma_kernel<64>,  cudaFuncAttributeMaxDynamicSharedMemorySize, SM64);

    // sgemm_mma smem: 2048 + 4*128*144 + 4*FOUT*144
    constexpr int SGM128 = 2048 + 4 * 128 * 144 + 4 * 128 * 144;  // 149504
    constexpr int SGM64  = 2048 + 4 * 128 * 144 + 4 * 64 * 144;   // 112640
    cudaFuncSetAttribute(sgemm_mma_kernel<128, 0>, cudaFuncAttributeMaxDynamicSharedMemorySize, SGM128);
    cudaFuncSetAttribute(sgemm_mma_kernel<128, 1>, cudaFuncAttributeMaxDynamicSharedMemorySize, SGM128);
    cudaFuncSetAttribute(sgemm_mma_kernel<64, 1>,  cudaFuncAttributeMaxDynamicSharedMemorySize, SGM64);

    build_mask_kernel<<<16384, 256>>>(adj);

    // layer 1 (128 -> 128): reads x directly
    sgemm_mma_kernel<128, 0><<<128, 256, SGM128>>>(x, W1, a1s, a1d, hh);
    attn_mma_kernel<128><<<dim3(IGROUPS, 8, ZSPLIT), 512, SM128>>>(hh);

    // layer 2 (128 -> 128): reads fused layer-1 fp16 partials
    sgemm_mma_kernel<128, 1><<<128, 256, SGM128>>>(nullptr, W2, a2s, a2d, hh);
    attn_mma_kernel<128><<<dim3(IGROUPS, 8, ZSPLIT), 512, SM128>>>(hh);

    // layer 3 (128 -> 64): reads fused layer-2 fp16 partials
    sgemm_mma_kernel<64, 1><<<128, 256, SGM64>>>(nullptr, W3, a3s, a3d, hh);
    attn_mma_kernel<64><<<dim3(IGROUPS, 8, ZSPLIT), 512, SM64>>>(hh);

    // final linear (fused layer-3 combine)
    final_partial_kernel<<<256, 128>>>(Wlin);
    final_reduce_kernel<<<4, 256>>>(blin, (float*)d_out);
}